// round 1
// baseline (speedup 1.0000x reference)
#include <cuda_runtime.h>

#define VOCAB 100000
#define BATCH 2048
#define SEQ   50
#define HID   256
#define KIN   512

// ---------------- scratch (device globals; no allocation allowed) ----------
__device__ float g_bow_h[BATCH * HID];
__device__ float g_beo_h[BATCH * HID];

// ============================================================================
// K1: bow path — dedup 50 tokens per row, gather-sum rows of W_bow_h,
//     bias + leaky -> g_bow_h.  One block per batch row, 256 threads (1/dim).
// ============================================================================
__global__ __launch_bounds__(256) void bow_gather_kernel(
    const unsigned int* __restrict__ s_words,   // raw 32-bit view of s
    const float* __restrict__ Wh,               // [VOCAB, 256]
    const float* __restrict__ bh)               // [256]
{
    __shared__ unsigned int wbuf[SEQ];
    __shared__ int toks[SEQ];
    __shared__ int uniq[SEQ];
    __shared__ int sh_n;
    __shared__ int sh_is64;

    const int b   = blockIdx.x;
    const int tid = threadIdx.x;

    // Phase 1: load the 50 words that are valid under BOTH int32/int64 layouts
    if (tid < SEQ) wbuf[tid] = s_words[b * SEQ + tid];
    __syncthreads();

    // Phase 2: dtype detection. Under int64 (tokens < 2^31), every odd word in
    // this window is a zero high-half. Under int32 they are uniform tokens.
    if (tid == 0) {
        int all0 = 1;
        #pragma unroll
        for (int i = 1; i < SEQ; i += 2) all0 &= (wbuf[i] == 0u);
        sh_is64 = all0;
    }
    __syncthreads();

    // Phase 3: fetch tokens under the detected layout
    if (tid < SEQ) {
        toks[tid] = sh_is64 ? (int)s_words[2 * (b * SEQ + tid)]
                            : (int)wbuf[tid];
    }
    __syncthreads();

    // Phase 4: dedup (scatter .set semantics: duplicates count once)
    if (tid == 0) {
        int n = 0;
        for (int i = 0; i < SEQ; i++) {
            int t = toks[i];
            bool dup = false;
            for (int j = 0; j < n; j++) if (uniq[j] == t) { dup = true; break; }
            if (!dup) uniq[n++] = t;
        }
        sh_n = n;
    }
    __syncthreads();

    // Phase 5: gather-sum. 4 independent accumulator chains for MLP.
    const int n = sh_n;
    float a0 = 0.f, a1 = 0.f, a2 = 0.f, a3 = 0.f;
    int i = 0;
    for (; i + 4 <= n; i += 4) {
        a0 += Wh[uniq[i + 0] * HID + tid];
        a1 += Wh[uniq[i + 1] * HID + tid];
        a2 += Wh[uniq[i + 2] * HID + tid];
        a3 += Wh[uniq[i + 3] * HID + tid];
    }
    for (; i < n; i++) a0 += Wh[uniq[i] * HID + tid];

    float acc = ((a0 + a1) + (a2 + a3)) + bh[tid];
    g_bow_h[b * HID + tid] = (acc > 0.f) ? acc : 0.2f * acc;
}

// ============================================================================
// K2: beo_h = leaky(x @ W_beo_h + b).  M=2048, K=512, N=256 fp32.
//     BM=32, BN=64, BK=32; 128 threads; thread tile 4x4; packed f32x2 FMA.
//     Grid (4, 64) = 256 blocks.
// ============================================================================
#define BM 32
#define BN 64
#define BK 32

__global__ __launch_bounds__(128) void beo_gemm_kernel(
    const float* __restrict__ X,     // [2048, 512]
    const float* __restrict__ W,     // [512, 256]
    const float* __restrict__ bias)  // [256]
{
    __shared__ __align__(16) float As[BM][BK + 4];  // [m][k], stride 36 (16B ok)
    __shared__ __align__(16) float Bs[BK][BN];      // [k][n]

    const int tid = threadIdx.x;
    const int tx  = tid & 15;   // 0..15 -> 4 cols each
    const int ty  = tid >> 4;   // 0..7  -> 4 rows each
    const int m0  = blockIdx.y * BM;
    const int n0  = blockIdx.x * BN;

    unsigned long long acc[4][2];
    #pragma unroll
    for (int r = 0; r < 4; r++) { acc[r][0] = 0ull; acc[r][1] = 0ull; }

    for (int k0 = 0; k0 < KIN; k0 += BK) {
        // load A tile: 32x32 floats = 256 float4 / 128 thr
        #pragma unroll
        for (int f = tid; f < BM * BK / 4; f += 128) {
            int r  = f >> 3;          // 8 float4 per row
            int kq = f & 7;
            float4 v = *(const float4*)&X[(m0 + r) * KIN + k0 + kq * 4];
            *(float4*)&As[r][kq * 4] = v;
        }
        // load B tile: 32x64 floats = 512 float4 / 128 thr
        #pragma unroll
        for (int f = tid; f < BK * BN / 4; f += 128) {
            int kr = f >> 4;          // 16 float4 per row
            int nq = f & 15;
            float4 v = *(const float4*)&W[(k0 + kr) * HID + n0 + nq * 4];
            *(float4*)&Bs[kr][nq * 4] = v;
        }
        __syncthreads();

        #pragma unroll
        for (int k = 0; k < BK; k++) {
            unsigned long long pb0 = *(const unsigned long long*)&Bs[k][tx * 4];
            unsigned long long pb1 = *(const unsigned long long*)&Bs[k][tx * 4 + 2];
            #pragma unroll
            for (int r = 0; r < 4; r++) {
                float av = As[ty * 4 + r][k];
                unsigned long long pa;
                asm("mov.b64 %0, {%1, %1};" : "=l"(pa) : "f"(av));
                asm("fma.rn.f32x2 %0, %1, %2, %0;" : "+l"(acc[r][0]) : "l"(pa), "l"(pb0));
                asm("fma.rn.f32x2 %0, %1, %2, %0;" : "+l"(acc[r][1]) : "l"(pa), "l"(pb1));
            }
        }
        __syncthreads();
    }

    // epilogue: bias + leaky, store to g_beo_h
    const float4 bb = *(const float4*)&bias[n0 + tx * 4];
    #pragma unroll
    for (int r = 0; r < 4; r++) {
        float o0, o1, o2, o3;
        asm("mov.b64 {%0, %1}, %2;" : "=f"(o0), "=f"(o1) : "l"(acc[r][0]));
        asm("mov.b64 {%0, %1}, %2;" : "=f"(o2), "=f"(o3) : "l"(acc[r][1]));
        o0 += bb.x; o1 += bb.y; o2 += bb.z; o3 += bb.w;
        o0 = (o0 > 0.f) ? o0 : 0.2f * o0;
        o1 = (o1 > 0.f) ? o1 : 0.2f * o1;
        o2 = (o2 > 0.f) ? o2 : 0.2f * o2;
        o3 = (o3 > 0.f) ? o3 : 0.2f * o3;
        float4 v = make_float4(o0, o1, o2, o3);
        *(float4*)&g_beo_h[(m0 + ty * 4 + r) * HID + n0 + tx * 4] = v;
    }
}

// ============================================================================
// K3: epilogue matmuls. For side in {bow, beo}:
//     e = H @ W_embd + b_embd  [2048,64];  p = H @ W_pred + b_pred [2048,5]
//     Block: 32 rows, 128 threads, 4x4 register tile for embd; weights via L1.
//     Grid (64, 2).
// ============================================================================
#define EP_ROWS 32

__global__ __launch_bounds__(128) void epilogue_kernel(
    const float* __restrict__ We_bow, const float* __restrict__ be_bow,
    const float* __restrict__ Wp_bow, const float* __restrict__ bp_bow,
    const float* __restrict__ We_beo, const float* __restrict__ be_beo,
    const float* __restrict__ Wp_beo, const float* __restrict__ bp_beo,
    float* __restrict__ out)
{
    __shared__ __align__(16) float sh[EP_ROWS][260];

    const int side = blockIdx.y;
    const int row0 = blockIdx.x * EP_ROWS;
    const int tid  = threadIdx.x;

    const float* H  = side ? g_beo_h : g_bow_h;
    const float* We = side ? We_beo : We_bow;
    const float* be = side ? be_beo : be_bow;
    const float* Wp = side ? Wp_beo : Wp_bow;
    const float* bp = side ? bp_beo : bp_bow;

    // stage H tile [32][256] (float4 loads, padded stride 260)
    #pragma unroll
    for (int f = tid; f < EP_ROWS * 64; f += 128) {
        int r  = f >> 6;
        int cq = f & 63;
        float4 v = *(const float4*)&H[(row0 + r) * HID + cq * 4];
        *(float4*)&sh[r][cq * 4] = v;
    }
    __syncthreads();

    // embd: 32 rows x 64 cols, thread tile 4x4
    const int cg = tid & 15;   // cols cg*4 .. +3
    const int rg = tid >> 4;   // rows rg*4 .. +3
    float acc[4][4];
    #pragma unroll
    for (int i = 0; i < 4; i++)
        #pragma unroll
        for (int j = 0; j < 4; j++) acc[i][j] = 0.f;

    #pragma unroll 4
    for (int k = 0; k < HID; k++) {
        float4 w = *(const float4*)&We[k * 64 + cg * 4];
        #pragma unroll
        for (int i = 0; i < 4; i++) {
            float h = sh[rg * 4 + i][k];
            acc[i][0] += h * w.x;
            acc[i][1] += h * w.y;
            acc[i][2] += h * w.z;
            acc[i][3] += h * w.w;
        }
    }

    const float4 bb = *(const float4*)&be[cg * 4];
    const int ebase = side ? (BATCH * 64) : 0;
    #pragma unroll
    for (int i = 0; i < 4; i++) {
        int row = row0 + rg * 4 + i;
        float4 v = make_float4(acc[i][0] + bb.x, acc[i][1] + bb.y,
                               acc[i][2] + bb.z, acc[i][3] + bb.w);
        *(float4*)&out[ebase + row * 64 + cg * 4] = v;
    }

    // pred: 32 rows x 5 cols = 160 dots
    const int pbase = BATCH * 128 + (side ? BATCH * 5 : 0);
    for (int o = tid; o < EP_ROWS * 5; o += 128) {
        int r = o & 31;
        int j = o >> 5;  // 0..4
        float a = 0.f;
        #pragma unroll 4
        for (int k = 0; k < HID; k++) a += sh[r][k] * Wp[k * 5 + j];
        out[pbase + (row0 + r) * 5 + j] = a + bp[j];
    }
}

// ============================================================================
extern "C" void kernel_launch(void* const* d_in, const int* in_sizes, int n_in,
                              void* d_out, int out_size)
{
    const unsigned int* s_words = (const unsigned int*)d_in[0];
    const float* x        = (const float*)d_in[1];
    const float* W_bow_h  = (const float*)d_in[2];
    const float* b_bow_h  = (const float*)d_in[3];
    const float* W_bow_p  = (const float*)d_in[4];
    const float* b_bow_p  = (const float*)d_in[5];
    const float* W_bow_e  = (const float*)d_in[6];
    const float* b_bow_e  = (const float*)d_in[7];
    const float* W_beo_h  = (const float*)d_in[8];
    const float* b_beo_h  = (const float*)d_in[9];
    const float* W_beo_p  = (const float*)d_in[10];
    const float* b_beo_p  = (const float*)d_in[11];
    const float* W_beo_e  = (const float*)d_in[12];
    const float* b_beo_e  = (const float*)d_in[13];
    float* out = (float*)d_out;

    bow_gather_kernel<<<BATCH, 256>>>(s_words, W_bow_h, b_bow_h);

    dim3 g2(HID / BN, BATCH / BM);
    beo_gemm_kernel<<<g2, 128>>>(x, W_beo_h, b_beo_h);

    dim3 g3(BATCH / EP_ROWS, 2);
    epilogue_kernel<<<g3, 128>>>(W_bow_e, b_bow_e, W_bow_p, b_bow_p,
                                 W_beo_e, b_beo_e, W_beo_p, b_beo_p, out);
}

// round 2
// speedup vs baseline: 2.2394x; 2.2394x over previous
#include <cuda_runtime.h>

#define VOCAB 100000
#define BATCH 2048
#define SEQ   50
#define HID   256
#define KIN   512

// ---------------- scratch (device globals; no allocation allowed) ----------
__device__ float g_bow_h[BATCH * HID];
__device__ float g_beo_h[BATCH * HID];

// ============================================================================
// K1: bow path. 4 batch rows per block, 256 threads.
//  - parallel first-occurrence mask (no serial dedup, no compaction)
//  - float4 gathers, 64 threads per row, 4 fmaf chains per thread
// ============================================================================
#define G 4

__global__ __launch_bounds__(256) void bow_gather_kernel(
    const unsigned int* __restrict__ s_words,   // raw 32-bit view of s
    const float* __restrict__ Wh,               // [VOCAB, 256]
    const float* __restrict__ bh)               // [256]
{
    __shared__ unsigned int wbuf[G * SEQ];
    __shared__ int   toks[G][SEQ];
    __shared__ float keepf[G][SEQ];
    __shared__ int sh_is64;

    const int tid = threadIdx.x;
    const int wbase = blockIdx.x * (G * SEQ);   // token index of first token

    // Phase 1: read 200 words at int32 positions (in-bounds under both dtypes)
    if (tid < G * SEQ) wbuf[tid] = s_words[wbase + tid];
    __syncthreads();

    // Phase 2: dtype detect — under int64 every odd word here is a zero
    // high-half (wbase is even). Under int32 they are uniform random tokens.
    if (tid == 0) {
        int all0 = 1;
        #pragma unroll
        for (int i = 1; i < G * SEQ; i += 2) all0 &= (wbuf[i] == 0u);
        sh_is64 = all0;
    }
    __syncthreads();

    // Phase 3: tokens under detected layout
    if (tid < G * SEQ) {
        int r = tid / SEQ, j = tid % SEQ;
        toks[r][j] = sh_is64 ? (int)s_words[2 * (wbase + tid)]
                             : (int)wbuf[tid];
    }
    __syncthreads();

    // Phase 4: parallel keep mask (first occurrence wins -> set semantics)
    if (tid < G * SEQ) {
        int r = tid / SEQ, j = tid % SEQ;
        int t = toks[r][j];
        float k = 1.0f;
        for (int j2 = 0; j2 < j; j2++)
            if (toks[r][j2] == t) { k = 0.0f; break; }
        keepf[r][j] = k;
    }
    __syncthreads();

    // Phase 5: gather-sum, float4 per thread (64 threads per row)
    const int r  = tid >> 6;
    const int c4 = (tid & 63) * 4;
    const float* __restrict__ Wc = Wh + c4;

    float4 s0 = make_float4(0.f, 0.f, 0.f, 0.f);
    float4 s1 = s0, s2 = s0, s3 = s0;

    #pragma unroll
    for (int i = 0; i < 48; i += 4) {
        const float4 v0 = *(const float4*)(Wc + toks[r][i + 0] * HID);
        const float4 v1 = *(const float4*)(Wc + toks[r][i + 1] * HID);
        const float4 v2 = *(const float4*)(Wc + toks[r][i + 2] * HID);
        const float4 v3 = *(const float4*)(Wc + toks[r][i + 3] * HID);
        const float k0 = keepf[r][i + 0], k1 = keepf[r][i + 1];
        const float k2 = keepf[r][i + 2], k3 = keepf[r][i + 3];
        s0.x = fmaf(k0, v0.x, s0.x); s0.y = fmaf(k0, v0.y, s0.y);
        s0.z = fmaf(k0, v0.z, s0.z); s0.w = fmaf(k0, v0.w, s0.w);
        s1.x = fmaf(k1, v1.x, s1.x); s1.y = fmaf(k1, v1.y, s1.y);
        s1.z = fmaf(k1, v1.z, s1.z); s1.w = fmaf(k1, v1.w, s1.w);
        s2.x = fmaf(k2, v2.x, s2.x); s2.y = fmaf(k2, v2.y, s2.y);
        s2.z = fmaf(k2, v2.z, s2.z); s2.w = fmaf(k2, v2.w, s2.w);
        s3.x = fmaf(k3, v3.x, s3.x); s3.y = fmaf(k3, v3.y, s3.y);
        s3.z = fmaf(k3, v3.z, s3.z); s3.w = fmaf(k3, v3.w, s3.w);
    }
    {   // tail i = 48, 49
        const float4 v0 = *(const float4*)(Wc + toks[r][48] * HID);
        const float4 v1 = *(const float4*)(Wc + toks[r][49] * HID);
        const float k0 = keepf[r][48], k1 = keepf[r][49];
        s0.x = fmaf(k0, v0.x, s0.x); s0.y = fmaf(k0, v0.y, s0.y);
        s0.z = fmaf(k0, v0.z, s0.z); s0.w = fmaf(k0, v0.w, s0.w);
        s1.x = fmaf(k1, v1.x, s1.x); s1.y = fmaf(k1, v1.y, s1.y);
        s1.z = fmaf(k1, v1.z, s1.z); s1.w = fmaf(k1, v1.w, s1.w);
    }

    const float4 bb = *(const float4*)(bh + c4);
    float o0 = (s0.x + s1.x) + (s2.x + s3.x) + bb.x;
    float o1 = (s0.y + s1.y) + (s2.y + s3.y) + bb.y;
    float o2 = (s0.z + s1.z) + (s2.z + s3.z) + bb.z;
    float o3 = (s0.w + s1.w) + (s2.w + s3.w) + bb.w;
    o0 = (o0 > 0.f) ? o0 : 0.2f * o0;
    o1 = (o1 > 0.f) ? o1 : 0.2f * o1;
    o2 = (o2 > 0.f) ? o2 : 0.2f * o2;
    o3 = (o3 > 0.f) ? o3 : 0.2f * o3;
    *(float4*)&g_bow_h[(blockIdx.x * G + r) * HID + c4] =
        make_float4(o0, o1, o2, o3);
}

// ============================================================================
// K2: beo_h = leaky(x @ W_beo_h + b).  M=2048, K=512, N=256.
//     BM=32, BN=32, BK=64; 128 threads; thread tile 2x4; f32x2 FMA.
//     Grid (8, 64) = 512 blocks.
// ============================================================================
#define BM 32
#define BN 32
#define BK 64

__global__ __launch_bounds__(128) void beo_gemm_kernel(
    const float* __restrict__ X,     // [2048, 512]
    const float* __restrict__ W,     // [512, 256]
    const float* __restrict__ bias)  // [256]
{
    __shared__ __align__(16) float As[BM][BK + 4];  // [m][k]
    __shared__ __align__(16) float Bs[BK][BN];      // [k][n]

    const int tid = threadIdx.x;
    const int tx  = tid & 7;     // 8 col-groups * 4 cols
    const int ty  = tid >> 3;    // 16 row-groups * 2 rows
    const int m0  = blockIdx.y * BM;
    const int n0  = blockIdx.x * BN;

    unsigned long long acc[2][2];
    acc[0][0] = acc[0][1] = acc[1][0] = acc[1][1] = 0ull;

    for (int k0 = 0; k0 < KIN; k0 += BK) {
        // load A tile: 32x64 floats = 512 float4 / 128 thr = 4 each
        #pragma unroll
        for (int f = tid; f < BM * BK / 4; f += 128) {
            int r = f >> 4;          // 16 float4 per row
            int q = f & 15;
            float4 v = *(const float4*)&X[(m0 + r) * KIN + k0 + q * 4];
            *(float4*)&As[r][q * 4] = v;
        }
        // load B tile: 64x32 floats = 512 float4 / 128 thr = 4 each
        #pragma unroll
        for (int f = tid; f < BK * BN / 4; f += 128) {
            int kr = f >> 3;         // 8 float4 per row
            int nq = f & 7;
            float4 v = *(const float4*)&W[(k0 + kr) * HID + n0 + nq * 4];
            *(float4*)&Bs[kr][nq * 4] = v;
        }
        __syncthreads();

        #pragma unroll 16
        for (int k = 0; k < BK; k++) {
            unsigned long long pb0 = *(const unsigned long long*)&Bs[k][tx * 4];
            unsigned long long pb1 = *(const unsigned long long*)&Bs[k][tx * 4 + 2];
            float a0 = As[ty * 2 + 0][k];
            float a1 = As[ty * 2 + 1][k];
            unsigned long long pa0, pa1;
            asm("mov.b64 %0, {%1, %1};" : "=l"(pa0) : "f"(a0));
            asm("mov.b64 %0, {%1, %1};" : "=l"(pa1) : "f"(a1));
            asm("fma.rn.f32x2 %0, %1, %2, %0;" : "+l"(acc[0][0]) : "l"(pa0), "l"(pb0));
            asm("fma.rn.f32x2 %0, %1, %2, %0;" : "+l"(acc[0][1]) : "l"(pa0), "l"(pb1));
            asm("fma.rn.f32x2 %0, %1, %2, %0;" : "+l"(acc[1][0]) : "l"(pa1), "l"(pb0));
            asm("fma.rn.f32x2 %0, %1, %2, %0;" : "+l"(acc[1][1]) : "l"(pa1), "l"(pb1));
        }
        __syncthreads();
    }

    const float4 bb = *(const float4*)&bias[n0 + tx * 4];
    #pragma unroll
    for (int r = 0; r < 2; r++) {
        float o0, o1, o2, o3;
        asm("mov.b64 {%0, %1}, %2;" : "=f"(o0), "=f"(o1) : "l"(acc[r][0]));
        asm("mov.b64 {%0, %1}, %2;" : "=f"(o2), "=f"(o3) : "l"(acc[r][1]));
        o0 += bb.x; o1 += bb.y; o2 += bb.z; o3 += bb.w;
        o0 = (o0 > 0.f) ? o0 : 0.2f * o0;
        o1 = (o1 > 0.f) ? o1 : 0.2f * o1;
        o2 = (o2 > 0.f) ? o2 : 0.2f * o2;
        o3 = (o3 > 0.f) ? o3 : 0.2f * o3;
        *(float4*)&g_beo_h[(m0 + ty * 2 + r) * HID + n0 + tx * 4] =
            make_float4(o0, o1, o2, o3);
    }
}

// ============================================================================
// K3: epilogue matmuls for both sides.
//     16 rows/block, 256 threads, grid (128, 2) = 256 blocks.
// ============================================================================
#define EP_ROWS 16

__global__ __launch_bounds__(256) void epilogue_kernel(
    const float* __restrict__ We_bow, const float* __restrict__ be_bow,
    const float* __restrict__ Wp_bow, const float* __restrict__ bp_bow,
    const float* __restrict__ We_beo, const float* __restrict__ be_beo,
    const float* __restrict__ Wp_beo, const float* __restrict__ bp_beo,
    float* __restrict__ out)
{
    __shared__ __align__(16) float sh[EP_ROWS][HID + 4];

    const int side = blockIdx.y;
    const int row0 = blockIdx.x * EP_ROWS;
    const int tid  = threadIdx.x;

    const float* H  = side ? g_beo_h : g_bow_h;
    const float* We = side ? We_beo : We_bow;
    const float* be = side ? be_beo : be_bow;
    const float* Wp = side ? Wp_beo : Wp_bow;
    const float* bp = side ? bp_beo : bp_bow;

    // stage H tile [16][256] : 1024 float4 / 256 thr = 4 each
    #pragma unroll
    for (int f = tid; f < EP_ROWS * (HID / 4); f += 256) {
        int r  = f >> 6;
        int cq = f & 63;
        float4 v = *(const float4*)&H[(row0 + r) * HID + cq * 4];
        *(float4*)&sh[r][cq * 4] = v;
    }
    __syncthreads();

    // embd: 16 rows x 64 cols; thread = (row, 4 cols), f32x2
    const int row = tid >> 4;     // 16 rows
    const int cg  = tid & 15;     // 16 col-groups * 4 cols

    unsigned long long e0 = 0ull, e1 = 0ull;
    #pragma unroll 8
    for (int k = 0; k < HID; k++) {
        float h = sh[row][k];
        unsigned long long pw0 = *(const unsigned long long*)&We[k * 64 + cg * 4];
        unsigned long long pw1 = *(const unsigned long long*)&We[k * 64 + cg * 4 + 2];
        unsigned long long ph;
        asm("mov.b64 %0, {%1, %1};" : "=l"(ph) : "f"(h));
        asm("fma.rn.f32x2 %0, %1, %2, %0;" : "+l"(e0) : "l"(ph), "l"(pw0));
        asm("fma.rn.f32x2 %0, %1, %2, %0;" : "+l"(e1) : "l"(ph), "l"(pw1));
    }
    {
        float o0, o1, o2, o3;
        asm("mov.b64 {%0, %1}, %2;" : "=f"(o0), "=f"(o1) : "l"(e0));
        asm("mov.b64 {%0, %1}, %2;" : "=f"(o2), "=f"(o3) : "l"(e1));
        const float4 bb = *(const float4*)&be[cg * 4];
        const int ebase = side ? (BATCH * 64) : 0;
        *(float4*)&out[ebase + (row0 + row) * 64 + cg * 4] =
            make_float4(o0 + bb.x, o1 + bb.y, o2 + bb.z, o3 + bb.w);
    }

    // pred: 16 rows x 5 cols = 80 outputs on threads 0..79
    if (tid < EP_ROWS * 5) {
        int r = tid / 5;
        int j = tid % 5;
        float a = 0.f;
        #pragma unroll 8
        for (int k = 0; k < HID; k++) a = fmaf(sh[r][k], Wp[k * 5 + j], a);
        const int pbase = BATCH * 128 + (side ? BATCH * 5 : 0);
        out[pbase + (row0 + r) * 5 + j] = a + bp[j];
    }
}

// ============================================================================
extern "C" void kernel_launch(void* const* d_in, const int* in_sizes, int n_in,
                              void* d_out, int out_size)
{
    const unsigned int* s_words = (const unsigned int*)d_in[0];
    const float* x        = (const float*)d_in[1];
    const float* W_bow_h  = (const float*)d_in[2];
    const float* b_bow_h  = (const float*)d_in[3];
    const float* W_bow_p  = (const float*)d_in[4];
    const float* b_bow_p  = (const float*)d_in[5];
    const float* W_bow_e  = (const float*)d_in[6];
    const float* b_bow_e  = (const float*)d_in[7];
    const float* W_beo_h  = (const float*)d_in[8];
    const float* b_beo_h  = (const float*)d_in[9];
    const float* W_beo_p  = (const float*)d_in[10];
    const float* b_beo_p  = (const float*)d_in[11];
    const float* W_beo_e  = (const float*)d_in[12];
    const float* b_beo_e  = (const float*)d_in[13];
    float* out = (float*)d_out;

    bow_gather_kernel<<<BATCH / G, 256>>>(s_words, W_bow_h, b_bow_h);

    dim3 g2(HID / BN, BATCH / BM);
    beo_gemm_kernel<<<g2, 128>>>(x, W_beo_h, b_beo_h);

    dim3 g3(BATCH / EP_ROWS, 2);
    epilogue_kernel<<<g3, 256>>>(W_bow_e, b_bow_e, W_bow_p, b_bow_p,
                                 W_beo_e, b_beo_e, W_beo_p, b_beo_p, out);
}

// round 3
// speedup vs baseline: 2.7421x; 1.2245x over previous
#include <cuda_runtime.h>

#define VOCAB 100000
#define BATCH 2048
#define SEQ   50
#define HID   256
#define KIN   512

// ---------------- scratch (device globals; no allocation allowed) ----------
__device__ float g_bow_h[BATCH * HID];
__device__ float g_beo_h[BATCH * HID];

// ============================================================================
// Fused kernel: blocks [0, K2_BLOCKS) do the beo GEMM; blocks
// [K2_BLOCKS, K2_BLOCKS + K1_BLOCKS) do the bow gather. 256 threads each.
// ============================================================================
#define BM 64
#define BN 64
#define BK 32
#define K2_BLOCKS ((BATCH / BM) * (HID / BN))   // 32*4 = 128
#define K1_ROWS_PER_BLK 2
#define K1_BLOCKS (BATCH / K1_ROWS_PER_BLK)     // 1024

union SmemU {
    struct {                       // GEMM tiles
        float As[BM][BK + 4];
        float Bs[BK][BN];
    } g;
    struct {                       // bow gather scratch
        unsigned int wbuf[K1_ROWS_PER_BLK * SEQ];
        int   toks[K1_ROWS_PER_BLK][SEQ];
        float keep[K1_ROWS_PER_BLK][SEQ];
        float part[K1_ROWS_PER_BLK][HID];
        int   is64;
    } b;
};

__device__ __forceinline__ float lky(float v) {
    return (v > 0.f) ? v : 0.2f * v;
}

__global__ __launch_bounds__(256) void fused_hidden_kernel(
    const unsigned int* __restrict__ s_words,
    const float* __restrict__ Wh,    const float* __restrict__ bh,
    const float* __restrict__ X,     const float* __restrict__ W,
    const float* __restrict__ bias)
{
    __shared__ SmemU sm;
    const int tid = threadIdx.x;

    if (blockIdx.x < K2_BLOCKS) {
        // ------------------------- beo GEMM path ---------------------------
        const int bx = blockIdx.x;
        const int m0 = (bx >> 2) * BM;
        const int n0 = (bx & 3) * BN;
        const int tx = tid & 15;    // 16 col-groups * 4 cols
        const int ty = tid >> 4;    // 16 row-groups * 4 rows

        unsigned long long acc[4][2];
        #pragma unroll
        for (int r = 0; r < 4; r++) { acc[r][0] = 0ull; acc[r][1] = 0ull; }

        for (int k0 = 0; k0 < KIN; k0 += BK) {
            // A tile: 64x32 = 512 float4 / 256 thr = 2 each
            #pragma unroll
            for (int f = tid; f < BM * BK / 4; f += 256) {
                int r = f >> 3, q = f & 7;
                *(float4*)&sm.g.As[r][q * 4] =
                    *(const float4*)&X[(m0 + r) * KIN + k0 + q * 4];
            }
            // B tile: 32x64 = 512 float4 / 256 thr = 2 each
            #pragma unroll
            for (int f = tid; f < BK * BN / 4; f += 256) {
                int kr = f >> 4, nq = f & 15;
                *(float4*)&sm.g.Bs[kr][nq * 4] =
                    *(const float4*)&W[(k0 + kr) * HID + n0 + nq * 4];
            }
            __syncthreads();

            #pragma unroll
            for (int k = 0; k < BK; k++) {
                float4 bv = *(const float4*)&sm.g.Bs[k][tx * 4];
                unsigned long long pb0, pb1;
                asm("mov.b64 %0, {%1, %2};" : "=l"(pb0) : "f"(bv.x), "f"(bv.y));
                asm("mov.b64 %0, {%1, %2};" : "=l"(pb1) : "f"(bv.z), "f"(bv.w));
                #pragma unroll
                for (int r = 0; r < 4; r++) {
                    float av = sm.g.As[ty * 4 + r][k];
                    unsigned long long pa;
                    asm("mov.b64 %0, {%1, %1};" : "=l"(pa) : "f"(av));
                    asm("fma.rn.f32x2 %0, %1, %2, %0;" : "+l"(acc[r][0]) : "l"(pa), "l"(pb0));
                    asm("fma.rn.f32x2 %0, %1, %2, %0;" : "+l"(acc[r][1]) : "l"(pa), "l"(pb1));
                }
            }
            __syncthreads();
        }

        const float4 bb = *(const float4*)&bias[n0 + tx * 4];
        #pragma unroll
        for (int r = 0; r < 4; r++) {
            float o0, o1, o2, o3;
            asm("mov.b64 {%0, %1}, %2;" : "=f"(o0), "=f"(o1) : "l"(acc[r][0]));
            asm("mov.b64 {%0, %1}, %2;" : "=f"(o2), "=f"(o3) : "l"(acc[r][1]));
            *(float4*)&g_beo_h[(m0 + ty * 4 + r) * HID + n0 + tx * 4] =
                make_float4(lky(o0 + bb.x), lky(o1 + bb.y),
                            lky(o2 + bb.z), lky(o3 + bb.w));
        }
    } else {
        // ------------------------- bow gather path -------------------------
        const int kb    = blockIdx.x - K2_BLOCKS;          // 0..1023
        const int wbase = kb * (K1_ROWS_PER_BLK * SEQ);    // even

        // Phase 1: read 100 words (in-bounds under both dtypes)
        if (tid < K1_ROWS_PER_BLK * SEQ) sm.b.wbuf[tid] = s_words[wbase + tid];
        __syncthreads();

        // Phase 2: dtype detect (odd words all zero <=> int64)
        if (tid == 0) {
            int all0 = 1;
            #pragma unroll
            for (int i = 1; i < K1_ROWS_PER_BLK * SEQ; i += 2)
                all0 &= (sm.b.wbuf[i] == 0u);
            sm.b.is64 = all0;
        }
        __syncthreads();

        // Phase 3: tokens under detected layout
        const int is64 = sm.b.is64;
        if (tid < K1_ROWS_PER_BLK * SEQ) {
            int r = tid / SEQ, j = tid - r * SEQ;
            sm.b.toks[r][j] = is64 ? (int)s_words[2 * (wbase + tid)]
                                   : (int)sm.b.wbuf[tid];
        }
        __syncthreads();

        // Phase 4: first-occurrence keep mask (set semantics)
        if (tid < K1_ROWS_PER_BLK * SEQ) {
            int r = tid / SEQ, j = tid - r * SEQ;
            int t = sm.b.toks[r][j];
            float k = 1.0f;
            for (int j2 = 0; j2 < j; j2++)
                if (sm.b.toks[r][j2] == t) { k = 0.0f; break; }
            sm.b.keep[r][j] = k;
        }
        __syncthreads();

        // Phase 5: gather-sum; 2 rows x 2 halves x 64 col-threads
        const int r    = tid >> 7;            // row 0/1
        const int h    = (tid >> 6) & 1;      // token half
        const int c4   = (tid & 63) * 4;      // 4 fp32 cols
        const int jb   = h * (SEQ / 2);       // 0 or 25
        const float* __restrict__ Wc = Wh + c4;

        float4 sa[4];
        #pragma unroll
        for (int q = 0; q < 4; q++) sa[q] = make_float4(0.f, 0.f, 0.f, 0.f);

        #pragma unroll
        for (int i = 0; i < SEQ / 2; i++) {
            const float4 v = *(const float4*)(Wc + sm.b.toks[r][jb + i] * HID);
            const float  kf = sm.b.keep[r][jb + i];
            float4& a = sa[i & 3];
            a.x = fmaf(kf, v.x, a.x); a.y = fmaf(kf, v.y, a.y);
            a.z = fmaf(kf, v.z, a.z); a.w = fmaf(kf, v.w, a.w);
        }
        float4 t;
        t.x = (sa[0].x + sa[1].x) + (sa[2].x + sa[3].x);
        t.y = (sa[0].y + sa[1].y) + (sa[2].y + sa[3].y);
        t.z = (sa[0].z + sa[1].z) + (sa[2].z + sa[3].z);
        t.w = (sa[0].w + sa[1].w) + (sa[2].w + sa[3].w);

        if (h == 1) *(float4*)&sm.b.part[r][c4] = t;
        __syncthreads();
        if (h == 0) {
            const float4 p  = *(const float4*)&sm.b.part[r][c4];
            const float4 bb = *(const float4*)(bh + c4);
            *(float4*)&g_bow_h[(kb * K1_ROWS_PER_BLK + r) * HID + c4] =
                make_float4(lky(t.x + p.x + bb.x), lky(t.y + p.y + bb.y),
                            lky(t.z + p.z + bb.z), lky(t.w + p.w + bb.w));
        }
    }
}

// ============================================================================
// K3: epilogue matmuls for both sides. 8 rows/block, 256 threads,
//     grid (256, 2) = 512 blocks.
// ============================================================================
#define EP_ROWS 8

__global__ __launch_bounds__(256) void epilogue_kernel(
    const float* __restrict__ We_bow, const float* __restrict__ be_bow,
    const float* __restrict__ Wp_bow, const float* __restrict__ bp_bow,
    const float* __restrict__ We_beo, const float* __restrict__ be_beo,
    const float* __restrict__ Wp_beo, const float* __restrict__ bp_beo,
    float* __restrict__ out)
{
    __shared__ __align__(16) float sh[EP_ROWS][HID + 4];

    const int side = blockIdx.y;
    const int row0 = blockIdx.x * EP_ROWS;
    const int tid  = threadIdx.x;

    const float* H  = side ? g_beo_h : g_bow_h;
    const float* We = side ? We_beo : We_bow;
    const float* be = side ? be_beo : be_bow;
    const float* Wp = side ? Wp_beo : Wp_bow;
    const float* bp = side ? bp_beo : bp_bow;

    // stage H tile [8][256]: 512 float4 / 256 thr = 2 each
    #pragma unroll
    for (int f = tid; f < EP_ROWS * (HID / 4); f += 256) {
        int r = f >> 6, cq = f & 63;
        *(float4*)&sh[r][cq * 4] = *(const float4*)&H[(row0 + r) * HID + cq * 4];
    }
    __syncthreads();

    // embd: 8 rows x 64 cols; thread = (row, col-pair) -> 1 FMA2 per k
    const int row = tid >> 5;     // 8 rows
    const int cp  = tid & 31;     // 32 col pairs

    unsigned long long e = 0ull;
    #pragma unroll 8
    for (int k = 0; k < HID; k++) {
        float h = sh[row][k];
        unsigned long long pw = *(const unsigned long long*)&We[k * 64 + cp * 2];
        unsigned long long ph;
        asm("mov.b64 %0, {%1, %1};" : "=l"(ph) : "f"(h));
        asm("fma.rn.f32x2 %0, %1, %2, %0;" : "+l"(e) : "l"(ph), "l"(pw));
    }
    {
        float o0, o1;
        asm("mov.b64 {%0, %1}, %2;" : "=f"(o0), "=f"(o1) : "l"(e));
        const float2 bb = *(const float2*)&be[cp * 2];
        const int ebase = side ? (BATCH * 64) : 0;
        *(float2*)&out[ebase + (row0 + row) * 64 + cp * 2] =
            make_float2(o0 + bb.x, o1 + bb.y);
    }

    // pred: 8 rows x 5 cols = 40 outputs
    if (tid < EP_ROWS * 5) {
        int r = tid / 5, j = tid - r * 5;
        float a = 0.f;
        #pragma unroll 8
        for (int k = 0; k < HID; k++) a = fmaf(sh[r][k], Wp[k * 5 + j], a);
        const int pbase = BATCH * 128 + (side ? BATCH * 5 : 0);
        out[pbase + (row0 + r) * 5 + j] = a + bp[j];
    }
}

// ============================================================================
extern "C" void kernel_launch(void* const* d_in, const int* in_sizes, int n_in,
                              void* d_out, int out_size)
{
    const unsigned int* s_words = (const unsigned int*)d_in[0];
    const float* x        = (const float*)d_in[1];
    const float* W_bow_h  = (const float*)d_in[2];
    const float* b_bow_h  = (const float*)d_in[3];
    const float* W_bow_p  = (const float*)d_in[4];
    const float* b_bow_p  = (const float*)d_in[5];
    const float* W_bow_e  = (const float*)d_in[6];
    const float* b_bow_e  = (const float*)d_in[7];
    const float* W_beo_h  = (const float*)d_in[8];
    const float* b_beo_h  = (const float*)d_in[9];
    const float* W_beo_p  = (const float*)d_in[10];
    const float* b_beo_p  = (const float*)d_in[11];
    const float* W_beo_e  = (const float*)d_in[12];
    const float* b_beo_e  = (const float*)d_in[13];
    float* out = (float*)d_out;

    fused_hidden_kernel<<<K2_BLOCKS + K1_BLOCKS, 256>>>(
        s_words, W_bow_h, b_bow_h, x, W_beo_h, b_beo_h);

    dim3 g3(BATCH / EP_ROWS, 2);
    epilogue_kernel<<<g3, 256>>>(W_bow_e, b_bow_e, W_bow_p, b_bow_p,
                                 W_beo_e, b_beo_e, W_beo_p, b_beo_p, out);
}

// round 4
// speedup vs baseline: 3.4154x; 1.2455x over previous
#include <cuda_runtime.h>

#define VOCAB 100000
#define BATCH 2048
#define SEQ   50
#define HID   256
#define KIN   512

// ---------------- scratch (device globals; no allocation allowed) ----------
__device__ float g_bow_h[BATCH * HID];
__device__ float g_beo_h[BATCH * HID];

__device__ __forceinline__ float lky(float v) {
    return (v > 0.f) ? v : 0.2f * v;
}

// ============================================================================
// Fused kernel: blocks [0, K2_BLOCKS) do the beo GEMM; blocks
// [K2_BLOCKS, K2_BLOCKS + K1_BLOCKS) do the bow gather. 256 threads each.
// (unchanged from round 3 — it measured ~28us overlapped)
// ============================================================================
#define BM 64
#define BN 64
#define BK 32
#define K2_BLOCKS ((BATCH / BM) * (HID / BN))   // 128
#define K1_ROWS_PER_BLK 2
#define K1_BLOCKS (BATCH / K1_ROWS_PER_BLK)     // 1024

union SmemU {
    struct {                       // GEMM tiles
        float As[BM][BK + 4];
        float Bs[BK][BN];
    } g;
    struct {                       // bow gather scratch
        unsigned int wbuf[K1_ROWS_PER_BLK * SEQ];
        int   toks[K1_ROWS_PER_BLK][SEQ];
        float keep[K1_ROWS_PER_BLK][SEQ];
        float part[K1_ROWS_PER_BLK][HID];
        int   is64;
    } b;
};

__global__ __launch_bounds__(256) void fused_hidden_kernel(
    const unsigned int* __restrict__ s_words,
    const float* __restrict__ Wh,    const float* __restrict__ bh,
    const float* __restrict__ X,     const float* __restrict__ W,
    const float* __restrict__ bias)
{
    __shared__ SmemU sm;
    const int tid = threadIdx.x;

    if (blockIdx.x < K2_BLOCKS) {
        // ------------------------- beo GEMM path ---------------------------
        const int bx = blockIdx.x;
        const int m0 = (bx >> 2) * BM;
        const int n0 = (bx & 3) * BN;
        const int tx = tid & 15;
        const int ty = tid >> 4;

        unsigned long long acc[4][2];
        #pragma unroll
        for (int r = 0; r < 4; r++) { acc[r][0] = 0ull; acc[r][1] = 0ull; }

        for (int k0 = 0; k0 < KIN; k0 += BK) {
            #pragma unroll
            for (int f = tid; f < BM * BK / 4; f += 256) {
                int r = f >> 3, q = f & 7;
                *(float4*)&sm.g.As[r][q * 4] =
                    *(const float4*)&X[(m0 + r) * KIN + k0 + q * 4];
            }
            #pragma unroll
            for (int f = tid; f < BK * BN / 4; f += 256) {
                int kr = f >> 4, nq = f & 15;
                *(float4*)&sm.g.Bs[kr][nq * 4] =
                    *(const float4*)&W[(k0 + kr) * HID + n0 + nq * 4];
            }
            __syncthreads();

            #pragma unroll
            for (int k = 0; k < BK; k++) {
                float4 bv = *(const float4*)&sm.g.Bs[k][tx * 4];
                unsigned long long pb0, pb1;
                asm("mov.b64 %0, {%1, %2};" : "=l"(pb0) : "f"(bv.x), "f"(bv.y));
                asm("mov.b64 %0, {%1, %2};" : "=l"(pb1) : "f"(bv.z), "f"(bv.w));
                #pragma unroll
                for (int r = 0; r < 4; r++) {
                    float av = sm.g.As[ty * 4 + r][k];
                    unsigned long long pa;
                    asm("mov.b64 %0, {%1, %1};" : "=l"(pa) : "f"(av));
                    asm("fma.rn.f32x2 %0, %1, %2, %0;" : "+l"(acc[r][0]) : "l"(pa), "l"(pb0));
                    asm("fma.rn.f32x2 %0, %1, %2, %0;" : "+l"(acc[r][1]) : "l"(pa), "l"(pb1));
                }
            }
            __syncthreads();
        }

        const float4 bb = *(const float4*)&bias[n0 + tx * 4];
        #pragma unroll
        for (int r = 0; r < 4; r++) {
            float o0, o1, o2, o3;
            asm("mov.b64 {%0, %1}, %2;" : "=f"(o0), "=f"(o1) : "l"(acc[r][0]));
            asm("mov.b64 {%0, %1}, %2;" : "=f"(o2), "=f"(o3) : "l"(acc[r][1]));
            *(float4*)&g_beo_h[(m0 + ty * 4 + r) * HID + n0 + tx * 4] =
                make_float4(lky(o0 + bb.x), lky(o1 + bb.y),
                            lky(o2 + bb.z), lky(o3 + bb.w));
        }
    } else {
        // ------------------------- bow gather path -------------------------
        const int kb    = blockIdx.x - K2_BLOCKS;
        const int wbase = kb * (K1_ROWS_PER_BLK * SEQ);

        if (tid < K1_ROWS_PER_BLK * SEQ) sm.b.wbuf[tid] = s_words[wbase + tid];
        __syncthreads();

        if (tid == 0) {
            int all0 = 1;
            #pragma unroll
            for (int i = 1; i < K1_ROWS_PER_BLK * SEQ; i += 2)
                all0 &= (sm.b.wbuf[i] == 0u);
            sm.b.is64 = all0;
        }
        __syncthreads();

        const int is64 = sm.b.is64;
        if (tid < K1_ROWS_PER_BLK * SEQ) {
            int r = tid / SEQ, j = tid - r * SEQ;
            sm.b.toks[r][j] = is64 ? (int)s_words[2 * (wbase + tid)]
                                   : (int)sm.b.wbuf[tid];
        }
        __syncthreads();

        if (tid < K1_ROWS_PER_BLK * SEQ) {
            int r = tid / SEQ, j = tid - r * SEQ;
            int t = sm.b.toks[r][j];
            float k = 1.0f;
            for (int j2 = 0; j2 < j; j2++)
                if (sm.b.toks[r][j2] == t) { k = 0.0f; break; }
            sm.b.keep[r][j] = k;
        }
        __syncthreads();

        const int r    = tid >> 7;
        const int h    = (tid >> 6) & 1;
        const int c4   = (tid & 63) * 4;
        const int jb   = h * (SEQ / 2);
        const float* __restrict__ Wc = Wh + c4;

        float4 sa[4];
        #pragma unroll
        for (int q = 0; q < 4; q++) sa[q] = make_float4(0.f, 0.f, 0.f, 0.f);

        #pragma unroll
        for (int i = 0; i < SEQ / 2; i++) {
            const float4 v = *(const float4*)(Wc + sm.b.toks[r][jb + i] * HID);
            const float  kf = sm.b.keep[r][jb + i];
            float4& a = sa[i & 3];
            a.x = fmaf(kf, v.x, a.x); a.y = fmaf(kf, v.y, a.y);
            a.z = fmaf(kf, v.z, a.z); a.w = fmaf(kf, v.w, a.w);
        }
        float4 t;
        t.x = (sa[0].x + sa[1].x) + (sa[2].x + sa[3].x);
        t.y = (sa[0].y + sa[1].y) + (sa[2].y + sa[3].y);
        t.z = (sa[0].z + sa[1].z) + (sa[2].z + sa[3].z);
        t.w = (sa[0].w + sa[1].w) + (sa[2].w + sa[3].w);

        if (h == 1) *(float4*)&sm.b.part[r][c4] = t;
        __syncthreads();
        if (h == 0) {
            const float4 p  = *(const float4*)&sm.b.part[r][c4];
            const float4 bb = *(const float4*)(bh + c4);
            *(float4*)&g_bow_h[(kb * K1_ROWS_PER_BLK + r) * HID + c4] =
                make_float4(lky(t.x + p.x + bb.x), lky(t.y + p.y + bb.y),
                            lky(t.z + p.z + bb.z), lky(t.w + p.w + bb.w));
        }
    }
}

// ============================================================================
// K3 v2: epilogue. 16 rows/block, 256 threads, grid (128, 2).
//   - We staged in smem in 2 chunks of 128 k (32 KB, unioned with reducers)
//   - thread tile 2 rows x 4 cols x K-split-2 -> 4 independent FMA2 chains
//   - pred: 160 threads x K-split-2, 4 independent chains each
// ============================================================================
#define EPB 16

union EpSmem {
    float WeS[128][64];                      // 32 KB weight stage
    struct {
        float red[2][EPB][64];               // 8 KB embd K-partials
        float predred[160];                  // pred K-partials
    } r;
};

__global__ __launch_bounds__(256) void epilogue_kernel(
    const float* __restrict__ We_bow, const float* __restrict__ be_bow,
    const float* __restrict__ Wp_bow, const float* __restrict__ bp_bow,
    const float* __restrict__ We_beo, const float* __restrict__ be_beo,
    const float* __restrict__ Wp_beo, const float* __restrict__ bp_beo,
    float* __restrict__ out)
{
    __shared__ float sh[EPB][HID];           // 16 KB H stage (unpadded)
    __shared__ EpSmem u;

    const int side = blockIdx.y;
    const int row0 = blockIdx.x * EPB;
    const int tid  = threadIdx.x;

    const float* H  = side ? g_beo_h : g_bow_h;
    const float* We = side ? We_beo : We_bow;
    const float* be = side ? be_beo : be_bow;
    const float* Wp = side ? Wp_beo : Wp_bow;
    const float* bp = side ? bp_beo : bp_bow;

    // stage H tile [16][256]: 1024 float4 / 256 thr = 4 each
    #pragma unroll
    for (int f = tid; f < EPB * (HID / 4); f += 256) {
        int r = f >> 6, cq = f & 63;
        *(float4*)&sh[r][cq * 4] = *(const float4*)&H[(row0 + r) * HID + cq * 4];
    }

    const int cg = tid & 15;          // 16 col groups * 4 cols
    const int rg = (tid >> 4) & 7;    // 8 row groups * 2 rows
    const int kp = tid >> 7;          // K partition 0/1 (64 k per chunk each)

    unsigned long long acc[2][2];
    acc[0][0] = acc[0][1] = acc[1][0] = acc[1][1] = 0ull;

    #pragma unroll
    for (int kc = 0; kc < 2; kc++) {
        // stage We rows [kc*128, kc*128+128): 2048 float4 / 256 thr = 8 each
        #pragma unroll
        for (int f = tid; f < 128 * 16; f += 256) {
            int kr = f >> 4, nq = f & 15;
            *(float4*)&u.WeS[kr][nq * 4] =
                *(const float4*)&We[(kc * 128 + kr) * 64 + nq * 4];
        }
        __syncthreads();

        const int kb = kp * 64;
        #pragma unroll 8
        for (int k = 0; k < 64; k++) {
            const int kk = kb + k;               // k within chunk
            const int kg = kc * 128 + kk;        // global k
            float h0 = sh[rg * 2 + 0][kg];
            float h1 = sh[rg * 2 + 1][kg];
            unsigned long long pw0 = *(const unsigned long long*)&u.WeS[kk][cg * 4];
            unsigned long long pw1 = *(const unsigned long long*)&u.WeS[kk][cg * 4 + 2];
            unsigned long long ph0, ph1;
            asm("mov.b64 %0, {%1, %1};" : "=l"(ph0) : "f"(h0));
            asm("mov.b64 %0, {%1, %1};" : "=l"(ph1) : "f"(h1));
            asm("fma.rn.f32x2 %0, %1, %2, %0;" : "+l"(acc[0][0]) : "l"(ph0), "l"(pw0));
            asm("fma.rn.f32x2 %0, %1, %2, %0;" : "+l"(acc[0][1]) : "l"(ph0), "l"(pw1));
            asm("fma.rn.f32x2 %0, %1, %2, %0;" : "+l"(acc[1][0]) : "l"(ph1), "l"(pw0));
            asm("fma.rn.f32x2 %0, %1, %2, %0;" : "+l"(acc[1][1]) : "l"(ph1), "l"(pw1));
        }
        __syncthreads();   // all done with this WeS chunk
    }

    // ---- store embd K-partials (union now safe to reuse) ----
    #pragma unroll
    for (int r = 0; r < 2; r++) {
        float o0, o1, o2, o3;
        asm("mov.b64 {%0, %1}, %2;" : "=f"(o0), "=f"(o1) : "l"(acc[r][0]));
        asm("mov.b64 {%0, %1}, %2;" : "=f"(o2), "=f"(o3) : "l"(acc[r][1]));
        *(float4*)&u.r.red[kp][rg * 2 + r][cg * 4] = make_float4(o0, o1, o2, o3);
    }

    // ---- pred K-partials: 160 threads, 4 independent chains each ----
    if (tid < EPB * 10) {
        int r   = tid / 10;
        int rem = tid - r * 10;
        int j   = rem % 5;
        int kq  = rem / 5;
        const int kb = kq * 128;
        float a0 = 0.f, a1 = 0.f, a2 = 0.f, a3 = 0.f;
        #pragma unroll 4
        for (int k = 0; k < 128; k += 4) {
            a0 = fmaf(sh[r][kb + k + 0], Wp[(kb + k + 0) * 5 + j], a0);
            a1 = fmaf(sh[r][kb + k + 1], Wp[(kb + k + 1) * 5 + j], a1);
            a2 = fmaf(sh[r][kb + k + 2], Wp[(kb + k + 2) * 5 + j], a2);
            a3 = fmaf(sh[r][kb + k + 3], Wp[(kb + k + 3) * 5 + j], a3);
        }
        u.r.predred[tid] = (a0 + a1) + (a2 + a3);
    }
    __syncthreads();

    // ---- final combine + store ----
    {
        const int row = tid >> 4;
        const int c4  = (tid & 15) * 4;
        float4 p0 = *(const float4*)&u.r.red[0][row][c4];
        float4 p1 = *(const float4*)&u.r.red[1][row][c4];
        float4 bb = *(const float4*)&be[c4];
        const int ebase = side ? (BATCH * 64) : 0;
        *(float4*)&out[ebase + (row0 + row) * 64 + c4] =
            make_float4(p0.x + p1.x + bb.x, p0.y + p1.y + bb.y,
                        p0.z + p1.z + bb.z, p0.w + p1.w + bb.w);
    }
    if (tid < EPB * 5) {
        int r = tid / 5, j = tid - r * 5;
        float v = u.r.predred[r * 10 + j] + u.r.predred[r * 10 + 5 + j] + bp[j];
        const int pbase = BATCH * 128 + (side ? BATCH * 5 : 0);
        out[pbase + (row0 + r) * 5 + j] = v;
    }
}

// ============================================================================
extern "C" void kernel_launch(void* const* d_in, const int* in_sizes, int n_in,
                              void* d_out, int out_size)
{
    const unsigned int* s_words = (const unsigned int*)d_in[0];
    const float* x        = (const float*)d_in[1];
    const float* W_bow_h  = (const float*)d_in[2];
    const float* b_bow_h  = (const float*)d_in[3];
    const float* W_bow_p  = (const float*)d_in[4];
    const float* b_bow_p  = (const float*)d_in[5];
    const float* W_bow_e  = (const float*)d_in[6];
    const float* b_bow_e  = (const float*)d_in[7];
    const float* W_beo_h  = (const float*)d_in[8];
    const float* b_beo_h  = (const float*)d_in[9];
    const float* W_beo_p  = (const float*)d_in[10];
    const float* b_beo_p  = (const float*)d_in[11];
    const float* W_beo_e  = (const float*)d_in[12];
    const float* b_beo_e  = (const float*)d_in[13];
    float* out = (float*)d_out;

    fused_hidden_kernel<<<K2_BLOCKS + K1_BLOCKS, 256>>>(
        s_words, W_bow_h, b_bow_h, x, W_beo_h, b_beo_h);

    dim3 g3(BATCH / EPB, 2);
    epilogue_kernel<<<g3, 256>>>(W_bow_e, b_bow_e, W_bow_p, b_bow_p,
                                 W_beo_e, b_beo_e, W_beo_p, b_beo_p, out);
}